// round 16
// baseline (speedup 1.0000x reference)
#include <cuda_runtime.h>
#include <cuda_fp16.h>
#include <cstdint>

#define BB 4
#define NN 4096
#define KK 64
#define MM (NN*KK)
#define C1 64
#define C2 128
#define C3 256

// ---------------- scratch ---------------------------------------------------
__device__ int    g_swap;
__device__ int    g_idx[BB*NN*KK];
__device__ float  g_f[(size_t)BB*10*MM];           // 42 MB raw 10-dim features
__device__ __half g_y2h[(size_t)BB*C2*MM];         // 256 MB raw layer-1 out (fp16)
__device__ float  g_ymax[(size_t)BB*NN*C3];        // 16 MB  max_k raw layer-2
__device__ double g_mom[BB][65];                   // feature moments
__device__ double g_sd[3][BB*C3*2];                // sum,sumsq per layer
__device__ float  g_ms[3][BB*C3*2];                // mean,istd per layer
__device__ float  g_w0p[BB][C1*10];                // istd-scaled W0 per batch
__device__ float  g_b0[BB][C1];                    // -mean*istd per batch

// ---------------- helpers ----------------------------------------------------
__device__ __forceinline__ uint32_t packh2(float a, float b) {
    __half2 h = __floats2half2_rn(a, b);
    return *reinterpret_cast<uint32_t*>(&h);
}
__device__ __forceinline__ void mma16816(float* d, const uint32_t* a, const uint32_t* b) {
    asm volatile(
      "mma.sync.aligned.m16n8k16.row.col.f32.f16.f16.f32 "
      "{%0,%1,%2,%3}, {%4,%5,%6,%7}, {%8,%9}, {%0,%1,%2,%3};"
      : "+f"(d[0]), "+f"(d[1]), "+f"(d[2]), "+f"(d[3])
      : "r"(a[0]), "r"(a[1]), "r"(a[2]), "r"(a[3]), "r"(b[0]), "r"(b[1]));
}
__device__ __forceinline__ float wred(float v) {
    v += __shfl_xor_sync(0xffffffffu, v, 1);
    v += __shfl_xor_sync(0xffffffffu, v, 2);
    v += __shfl_xor_sync(0xffffffffu, v, 4);
    v += __shfl_xor_sync(0xffffffffu, v, 8);
    v += __shfl_xor_sync(0xffffffffu, v, 16);
    return v;
}

// ---------------- input detect / prep ---------------------------------------
__global__ void k_detect(const float* __restrict__ a) {
    __shared__ int neg;
    if (threadIdx.x == 0) neg = 0;
    __syncthreads();
    int f = 0;
    for (int i = threadIdx.x; i < BB*3*NN; i += 256) if (a[i] < 0.f) f = 1;
    if (f) neg = 1;
    __syncthreads();
    if (threadIdx.x == 0) g_swap = neg;
}

__global__ void k_prep() {
    int t = blockIdx.x * blockDim.x + threadIdx.x;
    if (t < 3*BB*C3*2) (&g_sd[0][0])[t] = 0.0;
    if (t < BB*65) (&g_mom[0][0])[t] = 0.0;
}

// ---------------- KNN: warp-ballot per point ---------------------------------
__global__ void k_knn(const float* __restrict__ cA, const float* __restrict__ cB) {
    const float* coords = g_swap ? cB : cA;
    __shared__ float sx[NN], sy[NN], sz[NN];
    const int warp = threadIdx.x >> 5, lane = threadIdx.x & 31;
    const int pid = blockIdx.x * 8 + warp;
    const int b = pid >> 12, n = pid & (NN - 1);
    const float* cb = coords + (size_t)b * 3 * NN;
    for (int i = threadIdx.x; i < NN; i += blockDim.x) {
        sx[i] = cb[i]; sy[i] = cb[NN + i]; sz[i] = cb[2*NN + i];
    }
    __syncthreads();
    const float px = sx[n], py = sy[n], pz = sz[n];
    int cnt = 0, j0 = 0;
    int* out = g_idx + (size_t)pid * KK;
    for (int base = 0; base < NN; base += 32) {
        int j = base + lane;
        float dx = sx[j] - px, dy = sy[j] - py, dz = sz[j] - pz;
        float d2 = __fadd_rn(__fadd_rn(__fmul_rn(dx,dx), __fmul_rn(dy,dy)), __fmul_rn(dz,dz));
        bool valid = !(d2 > 0.04f);
        unsigned m = __ballot_sync(0xffffffffu, valid);
        if (cnt == 0 && m) j0 = base + (__ffs(m) - 1);
        int pos = cnt + __popc(m & ((1u << lane) - 1u));
        if (valid && pos < KK) out[pos] = j;
        cnt += __popc(m);
        if (cnt >= KK) break;
    }
    if (cnt < KK)
        for (int t = cnt + lane; t < KK; t += 32) out[t] = j0;
}

// ---------------- features (10 channels only) --------------------------------
__device__ __forceinline__ float fangle(float ax,float ay,float az,
                                        float bx,float by,float bz) {
    float cx = ay*bz - az*by, cy = az*bx - ax*bz, cz = ax*by - ay*bx;
    return atan2f(sqrtf(cx*cx + cy*cy + cz*cz), ax*bx + ay*by + az*bz);
}

__global__ void k_feat(const float* __restrict__ cA, const float* __restrict__ cB) {
    const float* coords = g_swap ? cB : cA;
    const float* feats  = g_swap ? cA : cB;
    const int gid = blockIdx.x * blockDim.x + threadIdx.x;
    const int b = gid >> 18, m = gid & (MM - 1);
    const int n = m >> 6, k = m & 63;
    const float* cb = coords + (size_t)b * 3 * NN;
    const float* fb = feats  + (size_t)b * 3 * NN;
    const float px = cb[n], py = cb[NN+n], pz = cb[2*NN+n];
    const float ax = fb[n], ay = fb[NN+n], az = fb[2*NN+n];
    const int j = g_idx[((size_t)(b*NN + n))*KK + k];
    const float dx = cb[j]-px, dy = cb[NN+j]-py, dz = cb[2*NN+j]-pz;
    const float bx = fb[j], by = fb[NN+j], bz = fb[2*NN+j];
    float f[10];
    f[0]=px; f[1]=py; f[2]=pz; f[3]=dx; f[4]=dy; f[5]=dz;
    if (j == n) {
        // self column: XLA's +0-init sum makes the dot +0 -> atan2(0,+0)=0 always.
        f[6] = 0.f; f[7] = 0.f; f[9] = 0.f;
    } else {
        f[6] = fangle(ax,ay,az, dx,dy,dz);
        f[7] = fangle(bx,by,bz, dx,dy,dz);
        f[9] = sqrtf(dx*dx + dy*dy + dz*dz);
    }
    f[8] = fangle(ax,ay,az, bx,by,bz);
    float* fp = g_f + (size_t)b*10*MM + m;
#pragma unroll
    for (int c = 0; c < 10; c++) fp[(size_t)c * MM] = f[c];
}

// ---------------- feature moments: register-accumulated pass -----------------
__global__ void k_mom() {
    const int b = blockIdx.x >> 6;
    const int seg = blockIdx.x & 63;
    const float* Fb = g_f + (size_t)b*10*MM + (size_t)seg*(MM/64);
    const int tid = threadIdx.x, lane = tid & 31, warp = tid >> 5;
    float acc[65];
#pragma unroll
    for (int i = 0; i < 65; i++) acc[i] = 0.f;
    for (int i = tid; i < MM/64; i += 256) {
        float f[10];
#pragma unroll
        for (int c = 0; c < 10; c++) f[c] = Fb[(size_t)c*MM + i];
        int idx = 10;
#pragma unroll
        for (int c = 0; c < 10; c++) {
            acc[c] += f[c];
#pragma unroll
            for (int c2 = c; c2 < 10; c2++) acc[idx++] += f[c]*f[c2];
        }
    }
    __shared__ float sm[65][8];
#pragma unroll
    for (int i = 0; i < 65; i++) {
        float v = wred(acc[i]);
        if (lane == 0) sm[i][warp] = v;
    }
    __syncthreads();
    if (tid < 65) {
        float s = 0.f;
#pragma unroll
        for (int w = 0; w < 8; w++) s += sm[tid][w];
        atomicAdd(&g_mom[b][tid], (double)s);
    }
}

// ---------------- layer-0 stats from moments + scaled W0 ---------------------
__global__ void k_final0(const float* __restrict__ W0) {
    int t = threadIdx.x;                 // 256 = BB*C1
    int b = t >> 6, o = t & 63;
    const double inv = 1.0 / (double)MM;
    double mean = 0.0, ex2 = 0.0;
#pragma unroll
    for (int c = 0; c < 10; c++) {
        double w = (double)W0[o*10 + c];
        mean += w * g_mom[b][c];
#pragma unroll
        for (int c2 = c; c2 < 10; c2++) {
            double w2 = (double)W0[o*10 + c2];
            double mm2 = g_mom[b][10 + c*(21-c)/2 + (c2-c)];
            ex2 += (c == c2 ? 1.0 : 2.0) * w * w2 * mm2;
        }
    }
    mean *= inv; ex2 *= inv;
    double var = ex2 - mean*mean;
    if (var < 0.0) var = 0.0;
    float istd = (float)(1.0 / sqrt(var + 1e-5));
#pragma unroll
    for (int c = 0; c < 10; c++) g_w0p[b][o*10 + c] = W0[o*10 + c] * istd;
    g_b0[b][o] = (float)(-mean) * istd;
}

template<int C, int L>
__global__ void k_final() {
    int t = blockIdx.x * blockDim.x + threadIdx.x;
    if (t >= BB*C) return;
    const double inv = 1.0 / (double)MM;
    double mean = g_sd[L][2*t] * inv;
    double var  = g_sd[L][2*t+1] * inv - mean*mean;
    if (var < 0.0) var = 0.0;
    g_ms[L][2*t]   = (float)mean;
    g_ms[L][2*t+1] = (float)(1.0 / sqrt(var + 1e-5));
}

// ---------------- fused fp16 mma.sync m16n8k16 GEMM --------------------------
// COUTF = full output channels; COUT = channels per block (COUT-split for
// occupancy). LID1: A = relu(W0'*f+b0) from features, y2 -> fp16 + stats.
// LID2: A = relu(norm(y2h)), out = max over k per n + stats.
template<int CIN, int COUT, int COUTF, int LID, int MINB>
__global__ void __launch_bounds__(256, MINB) k_tgemm(const float* __restrict__ Wfull) {
    constexpr int KS = CIN/16;           // k-steps of 16
    constexpr int RT = COUT/64;          // 16-row tiles per warp
    constexpr int TILES = 8;             // n-groups per block
    constexpr int NP = CIN/8;            // k-pairs per thread per tile
    constexpr int HSN = CIN*32;          // words per HS buffer
    constexpr int NSPLIT = COUTF/COUT;
    extern __shared__ __align__(16) uint32_t dsm[];
    uint32_t* WS = dsm;                  // [COUT/16][KS][32][4] packed half2
    uint32_t* HS = dsm + COUT*CIN/2;     // 2 x packed A
    __shared__ float sm_sum[256], sm_sq[256];
    __shared__ float sm_ms[512];
    __shared__ float sm_w0p[C1*10], sm_b0[C1];
    __shared__ float sm_max[2][256];

    const int tid = threadIdx.x;
    const int lane = tid & 31, wid = tid >> 5;
    const int wrow = wid & 3, wcol = wid >> 2;
    const int b     = blockIdx.x / (512*NSPLIT);
    const int rest  = blockIdx.x % (512*NSPLIT);
    const int split = rest >> 9;
    const int blk   = rest & 511;
    const float* W = Wfull + (size_t)split*COUT*CIN;

    if (tid < 256) { sm_sum[tid] = 0.f; sm_sq[tid] = 0.f; }
    if (LID == 1) {
        for (int i = tid; i < C1*10; i += 256) sm_w0p[i] = g_w0p[b][i];
        if (tid < C1) sm_b0[tid] = g_b0[b][tid];
    } else {
        for (int i = tid; i < CIN*2; i += 256) sm_ms[i] = g_ms[LID-1][b*CIN*2 + i];
    }

    // stage W into fp16 fragment order
    for (int idx = tid; idx < COUT*CIN/2; idx += 256) {
        int cout = idx / (CIN/2), p = idx % (CIN/2);
        int rt = cout >> 4, r = cout & 15;
        int ks = p >> 3, q = p & 7;
        int ln = ((r & 7) << 2) | (q & 3);
        int rg = (r >> 3) | ((q >> 2) << 1);
        WS[((rt*KS + ks)*32 + ln)*4 + rg] = packh2(W[cout*CIN + 2*p], W[cout*CIN + 2*p + 1]);
    }

    const int pp0 = tid >> 6;            // base pair index (0..3)
    const int col = tid & 63;

    const float* Fb = g_f + (size_t)b*10*MM;                 // LID1
    const __half* Yb = g_y2h + (size_t)(b*CIN)*MM;           // LID2

    float rsum[RT][2], rsq[RT][2];
#pragma unroll
    for (int i = 0; i < RT; i++) { rsum[i][0]=rsum[i][1]=0.f; rsq[i][0]=rsq[i][1]=0.f; }

    float pf[10];                        // LID1 prefetch
    __half pb[2*NP];                     // LID2 prefetch (pairs)
    {
        const int m0 = blk*TILES*64;
        if (LID == 1) {
#pragma unroll
            for (int c = 0; c < 10; c++) pf[c] = Fb[(size_t)c*MM + m0 + col];
        } else {
#pragma unroll
            for (int i = 0; i < NP; i++) {
                int pp = pp0 + i*4;
                pb[2*i]   = Yb[(size_t)(2*pp  )*MM + m0 + col];
                pb[2*i+1] = Yb[(size_t)(2*pp+1)*MM + m0 + col];
            }
        }
    }
    __syncthreads();                     // WS + consts ready

    for (int t = 0; t < TILES; t++) {
        const int n  = blk*TILES + t;
        const int m0 = n*64;
        uint32_t* HB = HS + (t & 1)*HSN;

        // build packed A entries
        const int ct0 = col >> 3, cl0 = col & 7;
#pragma unroll
        for (int i = 0; i < NP; i++) {
            int pp = pp0 + i*4;
            int k0 = 2*pp;
            float v0, v1;
            if (LID == 1) {
                v0 = sm_b0[k0]; v1 = sm_b0[k0+1];
#pragma unroll
                for (int c = 0; c < 10; c++) {
                    v0 = fmaf(sm_w0p[k0*10 + c],      pf[c], v0);
                    v1 = fmaf(sm_w0p[(k0+1)*10 + c],  pf[c], v1);
                }
                v0 = fmaxf(0.f, v0); v1 = fmaxf(0.f, v1);
            } else {
                v0 = fmaxf(0.f, (__half2float(pb[2*i])   - sm_ms[2*k0])     * sm_ms[2*k0+1]);
                v1 = fmaxf(0.f, (__half2float(pb[2*i+1]) - sm_ms[2*(k0+1)]) * sm_ms[2*(k0+1)+1]);
            }
            int ks = pp >> 3, q = pp & 7;
            HB[((ct0*KS + ks)*32 + ((cl0<<2)|(q&3)))*2 + (q>>2)] = packh2(v0, v1);
        }
        __syncthreads();

        // prefetch next tile while MMAs run
        if (t + 1 < TILES) {
            const int m1 = m0 + 64;
            if (LID == 1) {
#pragma unroll
                for (int c = 0; c < 10; c++) pf[c] = Fb[(size_t)c*MM + m1 + col];
            } else {
#pragma unroll
                for (int i = 0; i < NP; i++) {
                    int pp = pp0 + i*4;
                    pb[2*i]   = Yb[(size_t)(2*pp  )*MM + m1 + col];
                    pb[2*i+1] = Yb[(size_t)(2*pp+1)*MM + m1 + col];
                }
            }
        }

        float d[RT][4][4];
#pragma unroll
        for (int i = 0; i < RT; i++)
#pragma unroll
            for (int ct = 0; ct < 4; ct++)
                { d[i][ct][0]=0.f; d[i][ct][1]=0.f; d[i][ct][2]=0.f; d[i][ct][3]=0.f; }

#pragma unroll
        for (int ks = 0; ks < KS; ks++) {
            uint32_t a[RT][4];
#pragma unroll
            for (int i = 0; i < RT; i++) {
                uint4 v4 = *(const uint4*)(WS + (((wrow*RT + i)*KS + ks)*32 + lane)*4);
                a[i][0]=v4.x; a[i][1]=v4.y; a[i][2]=v4.z; a[i][3]=v4.w;
            }
            uint32_t bf[4][2];
#pragma unroll
            for (int ct = 0; ct < 4; ct++) {
                uint2 v2 = *(const uint2*)(HB + (((wcol*4 + ct)*KS + ks)*32 + lane)*2);
                bf[ct][0]=v2.x; bf[ct][1]=v2.y;
            }
#pragma unroll
            for (int i = 0; i < RT; i++)
#pragma unroll
                for (int ct = 0; ct < 4; ct++)
                    mma16816(d[i][ct], a[i], bf[ct]);
        }

        if (LID == 1) {
#pragma unroll
            for (int i = 0; i < RT; i++) {
                int row0 = wrow*(COUT/4) + i*16 + (lane>>2);
#pragma unroll
                for (int ct = 0; ct < 4; ct++) {
                    int colb = m0 + wcol*32 + ct*8 + ((lane&3)<<1);
                    float2 lo = make_float2(d[i][ct][0], d[i][ct][1]);
                    float2 hi = make_float2(d[i][ct][2], d[i][ct][3]);
                    *(__half2*)(g_y2h + ((size_t)(b*COUTF) + split*COUT + row0  )*MM + colb) =
                        __floats2half2_rn(lo.x, lo.y);
                    *(__half2*)(g_y2h + ((size_t)(b*COUTF) + split*COUT + row0+8)*MM + colb) =
                        __floats2half2_rn(hi.x, hi.y);
                    rsum[i][0] += lo.x + lo.y; rsq[i][0] += lo.x*lo.x + lo.y*lo.y;
                    rsum[i][1] += hi.x + hi.y; rsq[i][1] += hi.x*hi.x + hi.y*hi.y;
                }
            }
        } else {
            float mv[RT][2];
#pragma unroll
            for (int i = 0; i < RT; i++) { mv[i][0] = -3.4e38f; mv[i][1] = -3.4e38f; }
#pragma unroll
            for (int i = 0; i < RT; i++)
#pragma unroll
                for (int ct = 0; ct < 4; ct++) {
                    float v0 = d[i][ct][0], v1 = d[i][ct][1];
                    float v2 = d[i][ct][2], v3 = d[i][ct][3];
                    mv[i][0] = fmaxf(mv[i][0], fmaxf(v0, v1));
                    mv[i][1] = fmaxf(mv[i][1], fmaxf(v2, v3));
                    rsum[i][0] += v0 + v1; rsq[i][0] += v0*v0 + v1*v1;
                    rsum[i][1] += v2 + v3; rsq[i][1] += v2*v2 + v3*v3;
                }
#pragma unroll
            for (int i = 0; i < RT; i++)
#pragma unroll
                for (int h = 0; h < 2; h++) {
                    float m = mv[i][h];
                    m = fmaxf(m, __shfl_xor_sync(0xffffffffu, m, 1));
                    m = fmaxf(m, __shfl_xor_sync(0xffffffffu, m, 2));
                    if ((lane & 3) == 0)
                        sm_max[wcol][wrow*(COUT/4) + i*16 + (lane>>2) + h*8] = m;
                }
            __syncthreads();
            if (tid < COUT)
                g_ymax[((size_t)b*NN + n)*C3 + split*COUT + tid] =
                    fmaxf(sm_max[0][tid], sm_max[1][tid]);
        }
    }

    // stats flush
#pragma unroll
    for (int i = 0; i < RT; i++)
#pragma unroll
        for (int h = 0; h < 2; h++) {
            float s = rsum[i][h], q = rsq[i][h];
            s += __shfl_xor_sync(0xffffffffu, s, 1);
            s += __shfl_xor_sync(0xffffffffu, s, 2);
            q += __shfl_xor_sync(0xffffffffu, q, 1);
            q += __shfl_xor_sync(0xffffffffu, q, 2);
            if ((lane & 3) == 0) {
                int row = wrow*(COUT/4) + i*16 + (lane>>2) + h*8;
                atomicAdd(&sm_sum[row], s);
                atomicAdd(&sm_sq[row], q);
            }
        }
    __syncthreads();
    for (int i = tid; i < COUT; i += 256) {
        atomicAdd(&g_sd[LID][(b*COUTF + split*COUT + i)*2+0], (double)sm_sum[i]);
        atomicAdd(&g_sd[LID][(b*COUTF + split*COUT + i)*2+1], (double)sm_sq[i]);
    }
}

// ---------------- final output: coalesced transpose ---------------------------
__global__ void k_out(float* __restrict__ out) {
    __shared__ float sm[32][257];
    const int tid = threadIdx.x, lane = tid & 31, wid = tid >> 5;
    const int b = blockIdx.x >> 7;
    const int n0 = (blockIdx.x & 127) * 32;
#pragma unroll 4
    for (int i = 0; i < 32; i++)
        sm[i][tid] = g_ymax[((size_t)b*NN + n0 + i)*C3 + tid];
    __syncthreads();
#pragma unroll 4
    for (int j = 0; j < 32; j++) {
        int cout = j*8 + wid;
        float mean = g_ms[2][(b*C3 + cout)*2], istd = g_ms[2][(b*C3 + cout)*2 + 1];
        float v = (sm[lane][cout] - mean) * istd;
        out[((size_t)(b*C3) + cout)*NN + n0 + lane] = fmaxf(v, 0.f);
    }
}

// ---------------- launch -------------------------------------------------------
extern "C" void kernel_launch(void* const* d_in, const int* in_sizes, int n_in,
                              void* d_out, int out_size) {
    const float *big0 = nullptr, *big1 = nullptr, *W0 = nullptr, *W1 = nullptr, *W2 = nullptr;
    for (int i = 0; i < n_in; i++) {
        int sz = in_sizes[i];
        const float* p = (const float*)d_in[i];
        if (sz == BB*3*NN) { if (!big0) big0 = p; else big1 = p; }
        else if (sz == 64*10)   W0 = p;
        else if (sz == 128*64)  W1 = p;
        else if (sz == 256*128) W2 = p;
    }
    float* out = (float*)d_out;

    const int DSM1 = (C2*C1/2 + 2*C1*32)*4;   // 32 KB
    const int DSM2 = (128*C2/2 + 2*C2*32)*4;  // 64 KB (COUT=128 split of C3)
    cudaFuncSetAttribute(k_tgemm<C1, C2, C2, 1, 3>, cudaFuncAttributeMaxDynamicSharedMemorySize, DSM1);
    cudaFuncSetAttribute(k_tgemm<C2, 128, C3, 2, 3>, cudaFuncAttributeMaxDynamicSharedMemorySize, DSM2);

    k_detect<<<1, 256>>>(big0);
    k_prep<<<32, 256>>>();
    k_knn<<<(BB*NN)/8, 256>>>(big0, big1);
    k_feat<<<(BB*MM)/128, 128>>>(big0, big1);

    k_mom<<<BB*64, 256>>>();
    k_final0<<<1, 256>>>(W0);

    k_tgemm<C1, C2, C2, 1, 3><<<BB*512, 256, DSM1>>>(W1);
    k_final<C2, 1><<<2, 256>>>();

    k_tgemm<C2, 128, C3, 2, 3><<<BB*1024, 256, DSM2>>>(W2);
    k_final<C3, 2><<<4, 256>>>();

    k_out<<<BB*128, 256>>>(out);
}

// round 17
// speedup vs baseline: 1.1771x; 1.1771x over previous
#include <cuda_runtime.h>
#include <cuda_fp16.h>
#include <cstdint>

#define BB 4
#define NN 4096
#define KK 64
#define MM (NN*KK)
#define C1 64
#define C2 128
#define C3 256

// ---------------- scratch ---------------------------------------------------
__device__ int    g_swap;
__device__ int    g_idx[BB*NN*KK];
__device__ float  g_f[(size_t)BB*10*MM];           // 42 MB raw 10-dim features
__device__ __half g_y2h[(size_t)BB*C2*MM];         // 256 MB raw layer-1 out (fp16)
__device__ float  g_ymax[(size_t)BB*NN*C3];        // 16 MB  max_k raw layer-2
__device__ double g_mom[BB][65];                   // feature moments
__device__ double g_sd[3][BB*C3*2];                // sum,sumsq per layer
__device__ float  g_ms[3][BB*C3*2];                // mean,istd per layer
__device__ float  g_w0p[BB][C1*10];                // istd-scaled W0 per batch
__device__ float  g_b0[BB][C1];                    // -mean*istd per batch

// ---------------- helpers ----------------------------------------------------
__device__ __forceinline__ uint32_t packh2(float a, float b) {
    __half2 h = __floats2half2_rn(a, b);
    return *reinterpret_cast<uint32_t*>(&h);
}
__device__ __forceinline__ void mma16816(float* d, const uint32_t* a, const uint32_t* b) {
    asm volatile(
      "mma.sync.aligned.m16n8k16.row.col.f32.f16.f16.f32 "
      "{%0,%1,%2,%3}, {%4,%5,%6,%7}, {%8,%9}, {%0,%1,%2,%3};"
      : "+f"(d[0]), "+f"(d[1]), "+f"(d[2]), "+f"(d[3])
      : "r"(a[0]), "r"(a[1]), "r"(a[2]), "r"(a[3]), "r"(b[0]), "r"(b[1]));
}
__device__ __forceinline__ float wred(float v) {
    v += __shfl_xor_sync(0xffffffffu, v, 1);
    v += __shfl_xor_sync(0xffffffffu, v, 2);
    v += __shfl_xor_sync(0xffffffffu, v, 4);
    v += __shfl_xor_sync(0xffffffffu, v, 8);
    v += __shfl_xor_sync(0xffffffffu, v, 16);
    return v;
}

// ---------------- prep: zero stats + input-order detect ----------------------
__global__ void k_prep(const float* __restrict__ a) {
    int t = blockIdx.x * blockDim.x + threadIdx.x;
    if (t < 3*BB*C3*2) (&g_sd[0][0])[t] = 0.0;
    if (t < BB*65) (&g_mom[0][0])[t] = 0.0;
    if (blockIdx.x == 0) {
        __shared__ int neg;
        if (threadIdx.x == 0) neg = 0;
        __syncthreads();
        int f = 0;
        for (int i = threadIdx.x; i < BB*3*NN; i += 256) if (a[i] < 0.f) f = 1;
        if (f) neg = 1;
        __syncthreads();
        if (threadIdx.x == 0) g_swap = neg;   // first big array has negatives -> feats
    }
}

// ---------------- KNN: warp-ballot per point ---------------------------------
__global__ void k_knn(const float* __restrict__ cA, const float* __restrict__ cB) {
    const float* coords = g_swap ? cB : cA;
    __shared__ float sx[NN], sy[NN], sz[NN];
    const int warp = threadIdx.x >> 5, lane = threadIdx.x & 31;
    const int pid = blockIdx.x * 8 + warp;
    const int b = pid >> 12, n = pid & (NN - 1);
    const float* cb = coords + (size_t)b * 3 * NN;
    for (int i = threadIdx.x; i < NN; i += blockDim.x) {
        sx[i] = cb[i]; sy[i] = cb[NN + i]; sz[i] = cb[2*NN + i];
    }
    __syncthreads();
    const float px = sx[n], py = sy[n], pz = sz[n];
    int cnt = 0, j0 = 0;
    int* out = g_idx + (size_t)pid * KK;
    for (int base = 0; base < NN; base += 32) {
        int j = base + lane;
        float dx = sx[j] - px, dy = sy[j] - py, dz = sz[j] - pz;
        float d2 = __fadd_rn(__fadd_rn(__fmul_rn(dx,dx), __fmul_rn(dy,dy)), __fmul_rn(dz,dz));
        bool valid = !(d2 > 0.04f);
        unsigned m = __ballot_sync(0xffffffffu, valid);
        if (cnt == 0 && m) j0 = base + (__ffs(m) - 1);
        int pos = cnt + __popc(m & ((1u << lane) - 1u));
        if (valid && pos < KK) out[pos] = j;
        cnt += __popc(m);
        if (cnt >= KK) break;
    }
    if (cnt < KK)
        for (int t = cnt + lane; t < KK; t += 32) out[t] = j0;
}

// ---------------- features (10 channels only) --------------------------------
__device__ __forceinline__ float fangle(float ax,float ay,float az,
                                        float bx,float by,float bz) {
    float cx = ay*bz - az*by, cy = az*bx - ax*bz, cz = ax*by - ay*bx;
    return atan2f(sqrtf(cx*cx + cy*cy + cz*cz), ax*bx + ay*by + az*bz);
}

__global__ void k_feat(const float* __restrict__ cA, const float* __restrict__ cB) {
    const float* coords = g_swap ? cB : cA;
    const float* feats  = g_swap ? cA : cB;
    const int gid = blockIdx.x * blockDim.x + threadIdx.x;
    const int b = gid >> 18, m = gid & (MM - 1);
    const int n = m >> 6, k = m & 63;
    const float* cb = coords + (size_t)b * 3 * NN;
    const float* fb = feats  + (size_t)b * 3 * NN;
    const float px = cb[n], py = cb[NN+n], pz = cb[2*NN+n];
    const float ax = fb[n], ay = fb[NN+n], az = fb[2*NN+n];
    const int j = g_idx[((size_t)(b*NN + n))*KK + k];
    const float dx = cb[j]-px, dy = cb[NN+j]-py, dz = cb[2*NN+j]-pz;
    const float bx = fb[j], by = fb[NN+j], bz = fb[2*NN+j];
    float f[10];
    f[0]=px; f[1]=py; f[2]=pz; f[3]=dx; f[4]=dy; f[5]=dz;
    if (j == n) {
        // self column: XLA's +0-init sum makes the dot +0 -> atan2(0,+0)=0 always.
        f[6] = 0.f; f[7] = 0.f; f[9] = 0.f;
    } else {
        f[6] = fangle(ax,ay,az, dx,dy,dz);
        f[7] = fangle(bx,by,bz, dx,dy,dz);
        f[9] = sqrtf(dx*dx + dy*dy + dz*dz);
    }
    f[8] = fangle(ax,ay,az, bx,by,bz);
    float* fp = g_f + (size_t)b*10*MM + m;
#pragma unroll
    for (int c = 0; c < 10; c++) fp[(size_t)c * MM] = f[c];
}

// ---------------- feature moments: register-accumulated pass -----------------
__global__ void k_mom() {
    const int b = blockIdx.x >> 6;
    const int seg = blockIdx.x & 63;
    const float* Fb = g_f + (size_t)b*10*MM + (size_t)seg*(MM/64);
    const int tid = threadIdx.x, lane = tid & 31, warp = tid >> 5;
    float acc[65];
#pragma unroll
    for (int i = 0; i < 65; i++) acc[i] = 0.f;
    for (int i = tid; i < MM/64; i += 256) {
        float f[10];
#pragma unroll
        for (int c = 0; c < 10; c++) f[c] = Fb[(size_t)c*MM + i];
        int idx = 10;
#pragma unroll
        for (int c = 0; c < 10; c++) {
            acc[c] += f[c];
#pragma unroll
            for (int c2 = c; c2 < 10; c2++) acc[idx++] += f[c]*f[c2];
        }
    }
    __shared__ float sm[65][8];
#pragma unroll
    for (int i = 0; i < 65; i++) {
        float v = wred(acc[i]);
        if (lane == 0) sm[i][warp] = v;
    }
    __syncthreads();
    if (tid < 65) {
        float s = 0.f;
#pragma unroll
        for (int w = 0; w < 8; w++) s += sm[tid][w];
        atomicAdd(&g_mom[b][tid], (double)s);
    }
}

// ---------------- layer-0 stats from moments + scaled W0 ---------------------
__global__ void k_final0(const float* __restrict__ W0) {
    int t = threadIdx.x;                 // 256 = BB*C1
    int b = t >> 6, o = t & 63;
    const double inv = 1.0 / (double)MM;
    double mean = 0.0, ex2 = 0.0;
#pragma unroll
    for (int c = 0; c < 10; c++) {
        double w = (double)W0[o*10 + c];
        mean += w * g_mom[b][c];
#pragma unroll
        for (int c2 = c; c2 < 10; c2++) {
            double w2 = (double)W0[o*10 + c2];
            double mm2 = g_mom[b][10 + c*(21-c)/2 + (c2-c)];
            ex2 += (c == c2 ? 1.0 : 2.0) * w * w2 * mm2;
        }
    }
    mean *= inv; ex2 *= inv;
    double var = ex2 - mean*mean;
    if (var < 0.0) var = 0.0;
    float istd = (float)(1.0 / sqrt(var + 1e-5));
#pragma unroll
    for (int c = 0; c < 10; c++) g_w0p[b][o*10 + c] = W0[o*10 + c] * istd;
    g_b0[b][o] = (float)(-mean) * istd;
}

template<int C, int L>
__global__ void k_final() {
    int t = blockIdx.x * blockDim.x + threadIdx.x;
    if (t >= BB*C) return;
    const double inv = 1.0 / (double)MM;
    double mean = g_sd[L][2*t] * inv;
    double var  = g_sd[L][2*t+1] * inv - mean*mean;
    if (var < 0.0) var = 0.0;
    g_ms[L][2*t]   = (float)mean;
    g_ms[L][2*t+1] = (float)(1.0 / sqrt(var + 1e-5));
}

// ---------------- fused fp16 mma.sync m16n8k16 GEMM --------------------------
// LID1: A = relu(W0'*f + b0) from 10 features, out y2 -> fp16 + stats.
// LID2: A = relu(norm(y2h)), out = max over k per n + stats.
template<int CIN, int COUT, int LID, int MINB, int TILES>
__global__ void __launch_bounds__(256, MINB) k_tgemm(const float* __restrict__ W) {
    constexpr int KS = CIN/16;           // k-steps of 16
    constexpr int RT = COUT/64;          // 16-row tiles per warp
    constexpr int NP = CIN/8;            // k-pairs per thread per tile
    constexpr int HSN = CIN*32;          // words per HS buffer
    constexpr int NBLK = NN/TILES;       // blocks per batch
    extern __shared__ __align__(16) uint32_t dsm[];
    uint32_t* WS = dsm;                  // [COUT/16][KS][32][4] packed half2
    uint32_t* HS = dsm + COUT*CIN/2;     // 2 x packed A
    __shared__ float sm_sum[256], sm_sq[256];
    __shared__ float sm_ms[512];
    __shared__ float sm_w0p[C1*10], sm_b0[C1];
    __shared__ float sm_max[2][256];

    const int tid = threadIdx.x;
    const int lane = tid & 31, wid = tid >> 5;
    const int wrow = wid & 3, wcol = wid >> 2;
    const int b   = blockIdx.x / NBLK;
    const int blk = blockIdx.x % NBLK;

    if (tid < 256) { sm_sum[tid] = 0.f; sm_sq[tid] = 0.f; }
    if (LID == 1) {
        for (int i = tid; i < C1*10; i += 256) sm_w0p[i] = g_w0p[b][i];
        if (tid < C1) sm_b0[tid] = g_b0[b][tid];
    } else {
        for (int i = tid; i < CIN*2; i += 256) sm_ms[i] = g_ms[LID-1][b*CIN*2 + i];
    }

    // stage W into fp16 fragment order: pair p -> (ks = p>>3, q = p&7)
    for (int idx = tid; idx < COUT*CIN/2; idx += 256) {
        int cout = idx / (CIN/2), p = idx % (CIN/2);
        int rt = cout >> 4, r = cout & 15;
        int ks = p >> 3, q = p & 7;
        int ln = ((r & 7) << 2) | (q & 3);
        int rg = (r >> 3) | ((q >> 2) << 1);
        WS[((rt*KS + ks)*32 + ln)*4 + rg] = packh2(W[cout*CIN + 2*p], W[cout*CIN + 2*p + 1]);
    }

    const int pp0 = tid >> 6;            // base pair index (0..3)
    const int col = tid & 63;

    const float* Fb = g_f + (size_t)b*10*MM;                 // LID1
    const __half* Yb = g_y2h + (size_t)(b*CIN)*MM;           // LID2

    float rsum[RT][2], rsq[RT][2];
#pragma unroll
    for (int i = 0; i < RT; i++) { rsum[i][0]=rsum[i][1]=0.f; rsq[i][0]=rsq[i][1]=0.f; }

    float pf[10];                        // LID1 prefetch
    __half pb[2*NP];                     // LID2 prefetch (pairs)
    {
        const int m0 = blk*TILES*64;
        if (LID == 1) {
#pragma unroll
            for (int c = 0; c < 10; c++) pf[c] = Fb[(size_t)c*MM + m0 + col];
        } else {
#pragma unroll
            for (int i = 0; i < NP; i++) {
                int pp = pp0 + i*4;
                pb[2*i]   = Yb[(size_t)(2*pp  )*MM + m0 + col];
                pb[2*i+1] = Yb[(size_t)(2*pp+1)*MM + m0 + col];
            }
        }
    }
    __syncthreads();                     // WS + consts ready

    for (int t = 0; t < TILES; t++) {
        const int n  = blk*TILES + t;
        const int m0 = n*64;
        uint32_t* HB = HS + (t & 1)*HSN;

        // build packed A entries
        const int ct0 = col >> 3, cl0 = col & 7;
#pragma unroll
        for (int i = 0; i < NP; i++) {
            int pp = pp0 + i*4;
            int k0 = 2*pp;
            float v0, v1;
            if (LID == 1) {
                v0 = sm_b0[k0]; v1 = sm_b0[k0+1];
#pragma unroll
                for (int c = 0; c < 10; c++) {
                    v0 = fmaf(sm_w0p[k0*10 + c],      pf[c], v0);
                    v1 = fmaf(sm_w0p[(k0+1)*10 + c],  pf[c], v1);
                }
                v0 = fmaxf(0.f, v0); v1 = fmaxf(0.f, v1);
            } else {
                v0 = fmaxf(0.f, (__half2float(pb[2*i])   - sm_ms[2*k0])     * sm_ms[2*k0+1]);
                v1 = fmaxf(0.f, (__half2float(pb[2*i+1]) - sm_ms[2*(k0+1)]) * sm_ms[2*(k0+1)+1]);
            }
            int ks = pp >> 3, q = pp & 7;
            HB[((ct0*KS + ks)*32 + ((cl0<<2)|(q&3)))*2 + (q>>2)] = packh2(v0, v1);
        }
        __syncthreads();

        // prefetch next tile while MMAs run
        if (t + 1 < TILES) {
            const int m1 = m0 + 64;
            if (LID == 1) {
#pragma unroll
                for (int c = 0; c < 10; c++) pf[c] = Fb[(size_t)c*MM + m1 + col];
            } else {
#pragma unroll
                for (int i = 0; i < NP; i++) {
                    int pp = pp0 + i*4;
                    pb[2*i]   = Yb[(size_t)(2*pp  )*MM + m1 + col];
                    pb[2*i+1] = Yb[(size_t)(2*pp+1)*MM + m1 + col];
                }
            }
        }

        float d[RT][4][4];
#pragma unroll
        for (int i = 0; i < RT; i++)
#pragma unroll
            for (int ct = 0; ct < 4; ct++)
                { d[i][ct][0]=0.f; d[i][ct][1]=0.f; d[i][ct][2]=0.f; d[i][ct][3]=0.f; }

#pragma unroll
        for (int ks = 0; ks < KS; ks++) {
            uint32_t a[RT][4];
#pragma unroll
            for (int i = 0; i < RT; i++) {
                uint4 v4 = *(const uint4*)(WS + (((wrow*RT + i)*KS + ks)*32 + lane)*4);
                a[i][0]=v4.x; a[i][1]=v4.y; a[i][2]=v4.z; a[i][3]=v4.w;
            }
            uint32_t bf[4][2];
#pragma unroll
            for (int ct = 0; ct < 4; ct++) {
                uint2 v2 = *(const uint2*)(HB + (((wcol*4 + ct)*KS + ks)*32 + lane)*2);
                bf[ct][0]=v2.x; bf[ct][1]=v2.y;
            }
#pragma unroll
            for (int i = 0; i < RT; i++)
#pragma unroll
                for (int ct = 0; ct < 4; ct++)
                    mma16816(d[i][ct], a[i], bf[ct]);
        }

        if (LID == 1) {
#pragma unroll
            for (int i = 0; i < RT; i++) {
                int row0 = wrow*(COUT/4) + i*16 + (lane>>2);
#pragma unroll
                for (int ct = 0; ct < 4; ct++) {
                    int colb = m0 + wcol*32 + ct*8 + ((lane&3)<<1);
                    float2 lo = make_float2(d[i][ct][0], d[i][ct][1]);
                    float2 hi = make_float2(d[i][ct][2], d[i][ct][3]);
                    *(__half2*)(g_y2h + ((size_t)(b*COUT)+row0  )*MM + colb) =
                        __floats2half2_rn(lo.x, lo.y);
                    *(__half2*)(g_y2h + ((size_t)(b*COUT)+row0+8)*MM + colb) =
                        __floats2half2_rn(hi.x, hi.y);
                    rsum[i][0] += lo.x + lo.y; rsq[i][0] += lo.x*lo.x + lo.y*lo.y;
                    rsum[i][1] += hi.x + hi.y; rsq[i][1] += hi.x*hi.x + hi.y*hi.y;
                }
            }
        } else {
            float mv[RT][2];
#pragma unroll
            for (int i = 0; i < RT; i++) { mv[i][0] = -3.4e38f; mv[i][1] = -3.4e38f; }
#pragma unroll
            for (int i = 0; i < RT; i++)
#pragma unroll
                for (int ct = 0; ct < 4; ct++) {
                    float v0 = d[i][ct][0], v1 = d[i][ct][1];
                    float v2 = d[i][ct][2], v3 = d[i][ct][3];
                    mv[i][0] = fmaxf(mv[i][0], fmaxf(v0, v1));
                    mv[i][1] = fmaxf(mv[i][1], fmaxf(v2, v3));
                    rsum[i][0] += v0 + v1; rsq[i][0] += v0*v0 + v1*v1;
                    rsum[i][1] += v2 + v3; rsq[i][1] += v2*v2 + v3*v3;
                }
#pragma unroll
            for (int i = 0; i < RT; i++)
#pragma unroll
                for (int h = 0; h < 2; h++) {
                    float m = mv[i][h];
                    m = fmaxf(m, __shfl_xor_sync(0xffffffffu, m, 1));
                    m = fmaxf(m, __shfl_xor_sync(0xffffffffu, m, 2));
                    if ((lane & 3) == 0)
                        sm_max[wcol][wrow*(COUT/4) + i*16 + (lane>>2) + h*8] = m;
                }
            __syncthreads();
            if (tid < COUT)
                g_ymax[((size_t)b*NN + n)*C3 + tid] = fmaxf(sm_max[0][tid], sm_max[1][tid]);
        }
    }

    // stats flush
#pragma unroll
    for (int i = 0; i < RT; i++)
#pragma unroll
        for (int h = 0; h < 2; h++) {
            float s = rsum[i][h], q = rsq[i][h];
            s += __shfl_xor_sync(0xffffffffu, s, 1);
            s += __shfl_xor_sync(0xffffffffu, s, 2);
            q += __shfl_xor_sync(0xffffffffu, q, 1);
            q += __shfl_xor_sync(0xffffffffu, q, 2);
            if ((lane & 3) == 0) {
                int row = wrow*(COUT/4) + i*16 + (lane>>2) + h*8;
                atomicAdd(&sm_sum[row], s);
                atomicAdd(&sm_sq[row], q);
            }
        }
    __syncthreads();
    for (int i = tid; i < COUT; i += 256) {
        atomicAdd(&g_sd[LID][(b*COUT+i)*2+0], (double)sm_sum[i]);
        atomicAdd(&g_sd[LID][(b*COUT+i)*2+1], (double)sm_sq[i]);
    }
}

// ---------------- final output: coalesced transpose ---------------------------
__global__ void k_out(float* __restrict__ out) {
    __shared__ float sm[32][257];
    const int tid = threadIdx.x, lane = tid & 31, wid = tid >> 5;
    const int b = blockIdx.x >> 7;
    const int n0 = (blockIdx.x & 127) * 32;
#pragma unroll 4
    for (int i = 0; i < 32; i++)
        sm[i][tid] = g_ymax[((size_t)b*NN + n0 + i)*C3 + tid];
    __syncthreads();
#pragma unroll 4
    for (int j = 0; j < 32; j++) {
        int cout = j*8 + wid;
        float mean = g_ms[2][(b*C3 + cout)*2], istd = g_ms[2][(b*C3 + cout)*2 + 1];
        float v = (sm[lane][cout] - mean) * istd;
        out[((size_t)(b*C3) + cout)*NN + n0 + lane] = fmaxf(v, 0.f);
    }
}

// ---------------- launch -------------------------------------------------------
extern "C" void kernel_launch(void* const* d_in, const int* in_sizes, int n_in,
                              void* d_out, int out_size) {
    const float *big0 = nullptr, *big1 = nullptr, *W0 = nullptr, *W1 = nullptr, *W2 = nullptr;
    for (int i = 0; i < n_in; i++) {
        int sz = in_sizes[i];
        const float* p = (const float*)d_in[i];
        if (sz == BB*3*NN) { if (!big0) big0 = p; else big1 = p; }
        else if (sz == 64*10)   W0 = p;
        else if (sz == 128*64)  W1 = p;
        else if (sz == 256*128) W2 = p;
    }
    float* out = (float*)d_out;

    const int DSM1 = (C2*C1/2 + 2*C1*32)*4;   // 32 KB
    const int DSM2 = (C3*C2/2 + 2*C2*32)*4;   // 96 KB -> occupancy 2
    cudaFuncSetAttribute(k_tgemm<C1, C2, 1, 2, 8>,  cudaFuncAttributeMaxDynamicSharedMemorySize, DSM1);
    cudaFuncSetAttribute(k_tgemm<C2, C3, 2, 2, 16>, cudaFuncAttributeMaxDynamicSharedMemorySize, DSM2);

    k_prep<<<32, 256>>>(big0);
    k_knn<<<(BB*NN)/8, 256>>>(big0, big1);
    k_feat<<<(BB*MM)/128, 128>>>(big0, big1);

    k_mom<<<BB*64, 256>>>();
    k_final0<<<1, 256>>>(W0);

    k_tgemm<C1, C2, 1, 2, 8><<<BB*512, 256, DSM1>>>(W1);
    k_final<C2, 1><<<2, 256>>>();

    k_tgemm<C2, C3, 2, 2, 16><<<BB*256, 256, DSM2>>>(W2);
    k_final<C3, 2><<<4, 256>>>();

    k_out<<<BB*128, 256>>>(out);
}